// round 13
// baseline (speedup 1.0000x reference)
#include <cuda_runtime.h>
#include <cuda_fp16.h>
#include <cstdint>
#include <math.h>

#define D       128
#define NMAX    8192
#define TAU_INV 10.0f
#define EX2K    14.4269504088896f   // TAU_INV * log2(e)
#define TM      128
#define NTT     64                  // tiles per dimension
#define NTILES_TRI (NTT * (NTT + 1) / 2)   // 2080
#define GMAIN   296                 // 2 CTAs per SM, persistent
#define GFIN    64                  // finalize blocks (128 rows each)

// scratch (device globals; no allocation allowed). g_cls/g_cnt/g_ticket are
// restored to zero by finalize's last block each run.
__device__ __half g_ph[NMAX * D];      // normalized rows, f16 (B operand)
__device__ __half g_phA[NMAX * D];     // normalized rows * EX2K, f16 (A operand)
__device__ float  g_S[NMAX];           // exp-sum accumulators (zeroed by prep)
__device__ float  g_cls[2][D];         // per-class vector sums (from f16 table)
__device__ int    g_cnt[2];
__device__ unsigned int g_ticket;

// ---------------------------------------------------------------------------
__device__ __forceinline__ uint32_t smem_u32(const void* p) {
    uint32_t a;
    asm("{ .reg .u64 t; cvta.to.shared.u64 t, %1; cvt.u32.u64 %0, t; }"
        : "=r"(a) : "l"(p));
    return a;
}
__device__ __forceinline__ void ldsm4(uint32_t r[4], uint32_t addr) {
    asm volatile("ldmatrix.sync.aligned.m8n8.x4.shared.b16 {%0,%1,%2,%3}, [%4];"
                 : "=r"(r[0]), "=r"(r[1]), "=r"(r[2]), "=r"(r[3]) : "r"(addr));
}
__device__ __forceinline__ void mma16816(float c[4], const uint32_t a[4],
                                         const uint32_t b[2]) {
    asm("mma.sync.aligned.m16n8k16.row.col.f32.f16.f16.f32 "
        "{%0,%1,%2,%3}, {%4,%5,%6,%7}, {%8,%9}, {%0,%1,%2,%3};"
        : "+f"(c[0]), "+f"(c[1]), "+f"(c[2]), "+f"(c[3])
        : "r"(a[0]), "r"(a[1]), "r"(a[2]), "r"(a[3]), "r"(b[0]), "r"(b[1]));
}
__device__ __forceinline__ void cp16(uint32_t saddr, const void* g) {
    asm volatile("cp.async.cg.shared.global [%0], [%1], 16;"
                 :: "r"(saddr), "l"(g) : "memory");
}
__device__ __forceinline__ float ex2(float x) {
    float r;
    asm("ex2.approx.f32 %0, %1;" : "=f"(r) : "f"(x));
    return r;
}
__device__ __forceinline__ void barh(int id) {   // half-CTA named barrier
    asm volatile("bar.sync %0, %1;" :: "r"(id), "r"(128) : "memory");
}
#define CP_COMMIT() asm volatile("cp.async.commit_group;" ::: "memory")
#define CP_WAIT(n)  asm volatile("cp.async.wait_group %0;" :: "n"(n) : "memory")

// smem layout: A 32KB, then per-half double-buffered 16KB B strips
#define A_OFF  0u
#define BOFF(h, b) (32768u + (uint32_t)(h) * 32768u + (uint32_t)(b) * 16384u)
#define SMEM_TOTAL 98304

// ---------------------------------------------------------------------------
// Kernel 1: pure streaming prep (R12, unchanged).
// ---------------------------------------------------------------------------
__global__ __launch_bounds__(256)
void prep_kernel(const float* __restrict__ zi,
                 const float* __restrict__ zj,
                 int B, float* __restrict__ out) {
    int warp = threadIdx.x >> 5, lane = threadIdx.x & 31;
    int row  = blockIdx.x * 8 + warp;
    if (blockIdx.x == 0 && threadIdx.x == 0) out[0] = 0.f;

    const float* src = (row < B) ? (zi + (size_t)row * D)
                                 : (zj + (size_t)(row - B) * D);
    float4 v = ((const float4*)src)[lane];
    float ss = v.x * v.x + v.y * v.y + v.z * v.z + v.w * v.w;
    #pragma unroll
    for (int o = 16; o > 0; o >>= 1) ss += __shfl_xor_sync(0xffffffffu, ss, o);
    float s = 1.f / fmaxf(sqrtf(ss), 1e-8f);
    float4 pn = make_float4(v.x * s, v.y * s, v.z * s, v.w * s);

    __half2 h0 = __floats2half2_rn(pn.x, pn.y);
    __half2 h1 = __floats2half2_rn(pn.z, pn.w);
    uint2 u;
    u.x = *reinterpret_cast<unsigned int*>(&h0);
    u.y = *reinterpret_cast<unsigned int*>(&h1);
    ((uint2*)(g_ph + (size_t)row * D))[lane] = u;

    __half2 a0 = __floats2half2_rn(pn.x * EX2K, pn.y * EX2K);
    __half2 a1 = __floats2half2_rn(pn.z * EX2K, pn.w * EX2K);
    uint2 ua;
    ua.x = *reinterpret_cast<unsigned int*>(&a0);
    ua.y = *reinterpret_cast<unsigned int*>(&a1);
    ((uint2*)(g_phA + (size_t)row * D))[lane] = ua;

    if (lane == 0) g_S[row] = 0.f;
}

// ---------------------------------------------------------------------------
__device__ __forceinline__ void load_tileA(uint32_t dst, int base, int tid) {
    for (int u = tid; u < TM * 16; u += 256) {
        int rr = u >> 4, cc = u & 15;
        cp16(dst + (uint32_t)rr * 256u + (uint32_t)((cc ^ (rr & 7)) << 4),
             g_phA + (size_t)(base + rr) * D + cc * 8);
    }
}
__device__ __forceinline__ void load_strip(uint32_t dst, int base, int htid) {
    for (int u = htid; u < 64 * 16; u += 128) {
        int rr = u >> 4, cc = u & 15;
        cp16(dst + (uint32_t)rr * 256u + (uint32_t)((cc ^ (rr & 7)) << 4),
             g_ph + (size_t)(base + rr) * D + cc * 8);
    }
}

// ---------------------------------------------------------------------------
// Kernel 2: persistent symmetric HMMA. Two independent 4-warp halves per CTA,
// each on its own 64-col strip with named-barrier sync -> 4 phase domains/SMSP.
// ---------------------------------------------------------------------------
__global__ __launch_bounds__(256, 2)
void main_kernel() {
    extern __shared__ char sm[];
    const uint32_t smb = smem_u32(sm);

    const int tid = threadIdx.x, lane = tid & 31, wid = tid >> 5;
    const int half = wid >> 2, htid = tid & 127;
    const int wl = wid & 3;
    const int warp_m = wl >> 1, warp_n = wl & 1;
    const int barid = 1 + half;

    const int lo = (int)(((long long)blockIdx.x * NTILES_TRI) / GMAIN);
    const int hi = (int)(((long long)(blockIdx.x + 1) * NTILES_TRI) / GMAIN);

    int r = 0;
    while ((r + 1) * (2 * NTT - r) / 2 <= lo) r++;
    int c = r + (lo - r * (2 * NTT - r + 1) / 2);

    // prologue: A panel (all threads) + this half's first strip; sync once.
    load_tileA(smb + A_OFF, r * TM, tid);
    load_strip(BOFF(half, 0) + smb, c * TM + half * 64, htid);
    CP_COMMIT();
    CP_WAIT(0);
    __syncthreads();

    // ldsm address precompute (A: rows 0..127, B: strip rows 0..63)
    const int g = lane >> 3;
    uint32_t a_off[4], a_msk[4];
    #pragma unroll
    for (int mt = 0; mt < 4; mt++) {
        int row = warp_m * 64 + mt * 16 + (g & 1) * 8 + (lane & 7);
        a_off[mt] = smb + A_OFF + (uint32_t)row * 256u;
        a_msk[mt] = (uint32_t)(row & 7);
    }
    const int a_cadd = g >> 1;
    uint32_t b_row[2], b_msk[2];
    #pragma unroll
    for (int nt2 = 0; nt2 < 2; nt2++) {
        int row = warp_n * 32 + nt2 * 16 + (g >> 1) * 8 + (lane & 7);
        b_row[nt2] = (uint32_t)row * 256u;
        b_msk[nt2] = (uint32_t)(row & 7);
    }
    const int b_cadd = g & 1;

#define AADDR(mt, ks) (a_off[mt] + (uint32_t)(((2 * (ks) + a_cadd) ^ a_msk[mt]) << 4))
#define BADDR(n2, ks) (bbase + b_row[n2] + (uint32_t)(((2 * (ks) + b_cadd) ^ b_msk[n2]) << 4))

    float es[8];
    #pragma unroll
    for (int s = 0; s < 8; s++) es[s] = 0.f;
    int parity = 0;
    int accr = r;

    for (int t = lo; t < hi; t++) {
        const int tr = r, tc = c;
        const bool isdiag = (tr == tc);
        int nr = r, nc = c + 1;
        if (nc == NTT) { nr = r + 1; nc = nr; }
        const bool havenext = (t + 1 < hi);

        // invariant entering iter: outstanding cp groups = {B(t)} (or {} after
        // a row-change / prologue, where B(t) was already waited + synced).
        barh(barid);                       // half done with t-1: safe to overwrite buf^1
        if (havenext) {
            load_strip(BOFF(half, parity ^ 1) + smb, nc * TM + half * 64, htid);
            CP_COMMIT();
            CP_WAIT(1);                    // completes B(t); B(t+1) in flight
        } else {
            CP_WAIT(0);
        }
        barh(barid);                       // B(t) visible half-wide

        // ---- GEMM (software-pipelined, unchanged per-warp stream) -----------
        const uint32_t bbase = BOFF(half, parity) + smb;
        float acc[4][4][4];
        #pragma unroll
        for (int mt = 0; mt < 4; mt++)
            #pragma unroll
            for (int nt = 0; nt < 4; nt++)
                #pragma unroll
                for (int k = 0; k < 4; k++) acc[mt][nt][k] = 0.f;

        uint32_t afb[2][4], bfb[2][2][4];
        ldsm4(bfb[0][0], BADDR(0, 0));
        ldsm4(bfb[0][1], BADDR(1, 0));
        ldsm4(afb[0], AADDR(0, 0));
        #pragma unroll
        for (int ks = 0; ks < 8; ks++) {
            const int kb = ks & 1;
            if (ks < 7) {
                ldsm4(bfb[kb ^ 1][0], BADDR(0, ks + 1));
                ldsm4(bfb[kb ^ 1][1], BADDR(1, ks + 1));
            }
            #pragma unroll
            for (int mt = 0; mt < 4; mt++) {
                const int ab = mt & 1;
                if (mt < 3)      ldsm4(afb[ab ^ 1], AADDR(mt + 1, ks));
                else if (ks < 7) ldsm4(afb[ab ^ 1], AADDR(0, ks + 1));
                #pragma unroll
                for (int nt = 0; nt < 4; nt++)
                    mma16816(acc[mt][nt], afb[ab], &bfb[kb][nt >> 1][(nt & 1) * 2]);
            }
        }

        // ---- epilogue: ex2, row + column sums --------------------------------
        float csl[8];
        #pragma unroll
        for (int s = 0; s < 8; s++) csl[s] = 0.f;
        #pragma unroll
        for (int nt = 0; nt < 4; nt++) {
            #pragma unroll
            for (int mt = 0; mt < 4; mt++) {
                #pragma unroll
                for (int q = 0; q < 4; q++) {
                    float e = ex2(acc[mt][nt][q]);
                    if (isdiag) {
                        int jl = half * 64 + warp_n * 32 + nt * 8 + (lane & 3) * 2 + (q & 1);
                        int il = warp_m * 64 + mt * 16 + (lane >> 2) + ((q < 2) ? 0 : 8);
                        if (jl == il) e = 0.f;
                    }
                    es[mt * 2 + (q >> 1)] += e;
                    csl[nt * 2 + (q & 1)] += e;
                }
            }
        }
        if (!isdiag) {
            int colBase = tc * TM + half * 64;
            #pragma unroll
            for (int s = 0; s < 8; s++) {
                float v = csl[s];
                v += __shfl_xor_sync(0xffffffffu, v, 4);
                v += __shfl_xor_sync(0xffffffffu, v, 8);
                v += __shfl_xor_sync(0xffffffffu, v, 16);
                if (lane < 4)
                    atomicAdd(&g_S[colBase + warp_n * 32 + (s >> 1) * 8 + lane * 2 + (s & 1)], v);
            }
        }

        // ---- row-panel change: flush es, reload shared A (both halves) -------
        if (havenext && nr != tr) {
            int rowBase = accr * TM;
            #pragma unroll
            for (int s = 0; s < 8; s++) {
                float e = es[s];
                e += __shfl_xor_sync(0xffffffffu, e, 1);
                e += __shfl_xor_sync(0xffffffffu, e, 2);
                if ((lane & 3) == 0)
                    atomicAdd(&g_S[rowBase + warp_m * 64 + (s >> 1) * 16 +
                                   (lane >> 2) + (s & 1) * 8], e);
                es[s] = 0.f;
            }
            accr = nr;
            __syncthreads();               // both halves done reading A
            load_tileA(smb + A_OFF, nr * TM, tid);
            CP_COMMIT();
            CP_WAIT(0);                    // also completes B(t+1)
            __syncthreads();               // A visible CTA-wide
        }
        r = nr; c = nc; parity ^= 1;
    }

    // final row flush — accr owns the es[] accumulations
    {
        int rowBase = accr * TM;
        #pragma unroll
        for (int s = 0; s < 8; s++) {
            float e = es[s];
            e += __shfl_xor_sync(0xffffffffu, e, 1);
            e += __shfl_xor_sync(0xffffffffu, e, 2);
            if ((lane & 3) == 0)
                atomicAdd(&g_S[rowBase + warp_m * 64 + (s >> 1) * 16 +
                               (lane >> 2) + (s & 1) * 8], e);
        }
    }
#undef AADDR
#undef BADDR
}

// ---------------------------------------------------------------------------
// Kernel 3: finalize (R12, unchanged): log-sum + class sums from f16 table +
// ticketed class-norm term; last block resets g_cls/g_cnt/g_ticket.
// ---------------------------------------------------------------------------
__global__ __launch_bounds__(256)
void finalize_kernel(const int* __restrict__ y, int B, float* __restrict__ out) {
    __shared__ float ws[8];
    __shared__ float cls_b[2][D];
    __shared__ int   cnt_b;
    __shared__ bool  is_last;
    int t = threadIdx.x, lane = t & 31, warp = t >> 5;
    if (t < 2 * D) ((float*)cls_b)[t] = 0.f;
    if (t == 0) cnt_b = 0;

    float local = 0.f;
    if (t < 128) local = logf(g_S[blockIdx.x * 128 + t]);
    #pragma unroll
    for (int o = 16; o > 0; o >>= 1) local += __shfl_xor_sync(0xffffffffu, local, o);
    if (lane == 0) ws[warp] = local;
    __syncthreads();
    if (t < 8) {
        float v = ws[t];
        #pragma unroll
        for (int o = 4; o > 0; o >>= 1) v += __shfl_xor_sync(0x000000ffu, v, o);
        if (t == 0) atomicAdd(out, v);
    }

    float a0[4] = {0.f, 0.f, 0.f, 0.f}, a1[4] = {0.f, 0.f, 0.f, 0.f};
    int   c1 = 0;
    int rb = blockIdx.x * 128 + warp * 16;
    #pragma unroll 4
    for (int i = 0; i < 16; i++) {
        int row = rb + i;
        int lbl = (row < B) ? y[row] : y[row - B];
        uint2 u = ((const uint2*)(g_ph + (size_t)row * D))[lane];
        __half2 h0 = *reinterpret_cast<__half2*>(&u.x);
        __half2 h1 = *reinterpret_cast<__half2*>(&u.y);
        float2 f0 = __half22float2(h0), f1 = __half22float2(h1);
        if (lbl) {
            a1[0] += f0.x; a1[1] += f0.y; a1[2] += f1.x; a1[3] += f1.y; c1++;
        } else {
            a0[0] += f0.x; a0[1] += f0.y; a0[2] += f1.x; a0[3] += f1.y;
        }
    }
    #pragma unroll
    for (int k = 0; k < 4; k++) {
        atomicAdd(&cls_b[0][lane * 4 + k], a0[k]);
        atomicAdd(&cls_b[1][lane * 4 + k], a1[k]);
    }
    if (lane == 0) atomicAdd(&cnt_b, c1);
    __syncthreads();
    if (t < 2 * D) atomicAdd(&((float*)g_cls)[t], ((float*)cls_b)[t]);
    if (t == 0) atomicAdd(&g_cnt[1], cnt_b);

    __threadfence();
    __syncthreads();
    if (t == 0) is_last = (atomicAdd(&g_ticket, 1u) == (unsigned)(GFIN - 1));
    __syncthreads();
    if (!is_last) return;
    __threadfence();

    if (warp < 2) {
        float4 cv = ((const float4*)(g_cls[warp]))[lane];
        float nsq = cv.x * cv.x + cv.y * cv.y + cv.z * cv.z + cv.w * cv.w;
        #pragma unroll
        for (int o = 16; o > 0; o >>= 1) nsq += __shfl_xor_sync(0xffffffffu, nsq, o);
        if (lane == 0) {
            float cnt = (warp == 1) ? (float)g_cnt[1] : (float)(NMAX - g_cnt[1]);
            atomicAdd(out, -TAU_INV * (nsq - cnt) / (cnt - 1.f));
        }
    }
    __syncthreads();
    if (t < 2 * D) ((float*)g_cls)[t] = 0.f;
    if (t < 2) g_cnt[t] = 0;
    if (t == 0) g_ticket = 0u;
}

// ---------------------------------------------------------------------------
extern "C" void kernel_launch(void* const* d_in, const int* in_sizes, int n_in,
                              void* d_out, int out_size) {
    const float* zi = (const float*)d_in[0];
    const float* zj = (const float*)d_in[1];
    const int*   y  = (const int*)d_in[2];
    int B = in_sizes[2];
    int N = 2 * B;

    prep_kernel<<<N / 8, 256>>>(zi, zj, B, (float*)d_out);

    cudaFuncSetAttribute(main_kernel, cudaFuncAttributeMaxDynamicSharedMemorySize,
                         SMEM_TOTAL);
    main_kernel<<<GMAIN, 256, SMEM_TOTAL>>>();

    finalize_kernel<<<GFIN, 256>>>(y, B, (float*)d_out);
}

// round 14
// speedup vs baseline: 1.0021x; 1.0021x over previous
#include <cuda_runtime.h>
#include <cuda_fp16.h>
#include <cstdint>
#include <math.h>

#define D       128
#define NMAX    8192
#define TAU_INV 10.0f
#define EX2K    14.4269504088896f   // TAU_INV * log2(e)
#define TM      128
#define NTT     64                  // tiles per dimension
#define NTILES_TRI (NTT * (NTT + 1) / 2)   // 2080
#define GMAIN   296                 // 2 CTAs per SM, persistent
#define GFIN    32                  // finalize blocks (256 rows each)

// scratch (device globals; no allocation allowed). g_cls/g_cnt/g_ticket are
// restored to zero by finalize's last block each run.
__device__ __half g_ph[NMAX * D];      // normalized rows, f16 (B operand)
__device__ __half g_phA[NMAX * D];     // normalized rows * EX2K, f16 (A operand)
__device__ float  g_S[NMAX];           // exp-sum accumulators (zeroed by prep)
__device__ float  g_cls[2][D];         // per-class vector sums (from f16 table)
__device__ int    g_cnt[2];
__device__ unsigned int g_ticket;

// ---------------------------------------------------------------------------
__device__ __forceinline__ uint32_t smem_u32(const void* p) {
    uint32_t a;
    asm("{ .reg .u64 t; cvta.to.shared.u64 t, %1; cvt.u32.u64 %0, t; }"
        : "=r"(a) : "l"(p));
    return a;
}
__device__ __forceinline__ void ldsm4(uint32_t r[4], uint32_t addr) {
    asm volatile("ldmatrix.sync.aligned.m8n8.x4.shared.b16 {%0,%1,%2,%3}, [%4];"
                 : "=r"(r[0]), "=r"(r[1]), "=r"(r[2]), "=r"(r[3]) : "r"(addr));
}
// non-volatile — lets ptxas schedule MMAs between/around the LDSMs.
__device__ __forceinline__ void mma16816(float c[4], const uint32_t a[4],
                                         const uint32_t b[2]) {
    asm("mma.sync.aligned.m16n8k16.row.col.f32.f16.f16.f32 "
        "{%0,%1,%2,%3}, {%4,%5,%6,%7}, {%8,%9}, {%0,%1,%2,%3};"
        : "+f"(c[0]), "+f"(c[1]), "+f"(c[2]), "+f"(c[3])
        : "r"(a[0]), "r"(a[1]), "r"(a[2]), "r"(a[3]), "r"(b[0]), "r"(b[1]));
}
__device__ __forceinline__ void cp16(uint32_t saddr, const void* g) {
    asm volatile("cp.async.cg.shared.global [%0], [%1], 16;"
                 :: "r"(saddr), "l"(g) : "memory");
}
// pack two f32 -> f16x2 (lo = first arg), exp2 on both halves, unpack to f32
__device__ __forceinline__ uint32_t pack_h2(float lo, float hi) {
    uint32_t r;
    asm("cvt.rn.f16x2.f32 %0, %1, %2;" : "=r"(r) : "f"(hi), "f"(lo));
    return r;
}
__device__ __forceinline__ uint32_t ex2_h2(uint32_t x) {
    uint32_t r;
    asm("ex2.approx.f16x2 %0, %1;" : "=r"(r) : "r"(x));
    return r;
}
#define CP_COMMIT() asm volatile("cp.async.commit_group;" ::: "memory")
#define CP_WAIT(n)  asm volatile("cp.async.wait_group %0;" :: "n"(n) : "memory")

#define A_OFF  0u
#define B0_OFF 32768u
#define B1_OFF 65536u
#define SMEM_TOTAL 98304

// ---------------------------------------------------------------------------
// Kernel 1: pure streaming prep (R12, unchanged).
// ---------------------------------------------------------------------------
__global__ __launch_bounds__(256)
void prep_kernel(const float* __restrict__ zi,
                 const float* __restrict__ zj,
                 int B, float* __restrict__ out) {
    int warp = threadIdx.x >> 5, lane = threadIdx.x & 31;
    int row  = blockIdx.x * 8 + warp;
    if (blockIdx.x == 0 && threadIdx.x == 0) out[0] = 0.f;

    const float* src = (row < B) ? (zi + (size_t)row * D)
                                 : (zj + (size_t)(row - B) * D);
    float4 v = ((const float4*)src)[lane];
    float ss = v.x * v.x + v.y * v.y + v.z * v.z + v.w * v.w;
    #pragma unroll
    for (int o = 16; o > 0; o >>= 1) ss += __shfl_xor_sync(0xffffffffu, ss, o);
    float s = 1.f / fmaxf(sqrtf(ss), 1e-8f);
    float4 pn = make_float4(v.x * s, v.y * s, v.z * s, v.w * s);

    __half2 h0 = __floats2half2_rn(pn.x, pn.y);
    __half2 h1 = __floats2half2_rn(pn.z, pn.w);
    uint2 u;
    u.x = *reinterpret_cast<unsigned int*>(&h0);
    u.y = *reinterpret_cast<unsigned int*>(&h1);
    ((uint2*)(g_ph + (size_t)row * D))[lane] = u;

    __half2 a0 = __floats2half2_rn(pn.x * EX2K, pn.y * EX2K);
    __half2 a1 = __floats2half2_rn(pn.z * EX2K, pn.w * EX2K);
    uint2 ua;
    ua.x = *reinterpret_cast<unsigned int*>(&a0);
    ua.y = *reinterpret_cast<unsigned int*>(&a1);
    ((uint2*)(g_phA + (size_t)row * D))[lane] = ua;

    if (lane == 0) g_S[row] = 0.f;
}

// ---------------------------------------------------------------------------
__device__ __forceinline__ void load_tile(uint32_t dst, const __half* table,
                                          int base, int tid) {
    for (int u = tid; u < TM * 16; u += 256) {
        int rr = u >> 4, cc = u & 15;
        cp16(dst + (uint32_t)rr * 256u + (uint32_t)((cc ^ (rr & 7)) << 4),
             table + (size_t)(base + rr) * D + cc * 8);
    }
}

// ---------------------------------------------------------------------------
// Kernel 2: persistent symmetric HMMA (R12 structure), f16x2 ex2 epilogue.
// ---------------------------------------------------------------------------
__global__ __launch_bounds__(256, 2)
void main_kernel() {
    extern __shared__ char sm[];
    const uint32_t smb = smem_u32(sm);

    const int tid = threadIdx.x, lane = tid & 31, wid = tid >> 5;
    const int warp_m = wid >> 2, warp_n = wid & 3;

    const int lo = (int)(((long long)blockIdx.x * NTILES_TRI) / GMAIN);
    const int hi = (int)(((long long)(blockIdx.x + 1) * NTILES_TRI) / GMAIN);

    int r = 0;
    while ((r + 1) * (2 * NTT - r) / 2 <= lo) r++;
    int c = r + (lo - r * (2 * NTT - r + 1) / 2);

    load_tile(smb + A_OFF, g_phA, r * TM, tid);
    load_tile(smb + B0_OFF, g_ph, c * TM, tid);
    CP_COMMIT();

    const int g = lane >> 3;
    uint32_t a_off[4], a_msk[4];
    #pragma unroll
    for (int mt = 0; mt < 4; mt++) {
        int row = warp_m * 64 + mt * 16 + (g & 1) * 8 + (lane & 7);
        a_off[mt] = smb + A_OFF + (uint32_t)row * 256u;
        a_msk[mt] = (uint32_t)(row & 7);
    }
    const int a_cadd = g >> 1;
    uint32_t b_row[2], b_msk[2];
    #pragma unroll
    for (int nt2 = 0; nt2 < 2; nt2++) {
        int row = warp_n * 32 + nt2 * 16 + (g >> 1) * 8 + (lane & 7);
        b_row[nt2] = (uint32_t)row * 256u;
        b_msk[nt2] = (uint32_t)(row & 7);
    }
    const int b_cadd = g & 1;

#define AADDR(mt, ks) (a_off[mt] + (uint32_t)(((2 * (ks) + a_cadd) ^ a_msk[mt]) << 4))
#define BADDR(n2, ks) (bbase + b_row[n2] + (uint32_t)(((2 * (ks) + b_cadd) ^ b_msk[n2]) << 4))

    float es[8];
    #pragma unroll
    for (int s = 0; s < 8; s++) es[s] = 0.f;
    int parity = 0;
    int accr = r;

    for (int t = lo; t < hi; t++) {
        const int tr = r, tc = c;
        const bool isdiag = (tr == tc);
        int nr = r, nc = c + 1;
        if (nc == NTT) { nr = r + 1; nc = nr; }
        const bool havenext = (t + 1 < hi);

        __syncthreads();
        if (havenext) {
            load_tile(smb + (parity ? B0_OFF : B1_OFF), g_ph, nc * TM, tid);
            CP_COMMIT();
            CP_WAIT(1);
        } else {
            CP_WAIT(0);
        }
        __syncthreads();

        const uint32_t bbase = smb + (parity ? B1_OFF : B0_OFF);
        float acc[4][4][4];
        #pragma unroll
        for (int mt = 0; mt < 4; mt++)
            #pragma unroll
            for (int nt = 0; nt < 4; nt++)
                #pragma unroll
                for (int k = 0; k < 4; k++) acc[mt][nt][k] = 0.f;

        uint32_t afb[2][4], bfb[2][2][4];
        ldsm4(bfb[0][0], BADDR(0, 0));
        ldsm4(bfb[0][1], BADDR(1, 0));
        ldsm4(afb[0], AADDR(0, 0));
        #pragma unroll
        for (int ks = 0; ks < 8; ks++) {
            const int kb = ks & 1;
            if (ks < 7) {
                ldsm4(bfb[kb ^ 1][0], BADDR(0, ks + 1));
                ldsm4(bfb[kb ^ 1][1], BADDR(1, ks + 1));
            }
            #pragma unroll
            for (int mt = 0; mt < 4; mt++) {
                const int ab = mt & 1;
                if (mt < 3)      ldsm4(afb[ab ^ 1], AADDR(mt + 1, ks));
                else if (ks < 7) ldsm4(afb[ab ^ 1], AADDR(0, ks + 1));
                #pragma unroll
                for (int nt = 0; nt < 4; nt++)
                    mma16816(acc[mt][nt], afb[ab], &bfb[kb][nt >> 1][(nt & 1) * 2]);
            }
        }

        // ---- epilogue: paired f16x2 ex2, row + column sums --------------------
        float csl[8];
        #pragma unroll
        for (int s = 0; s < 8; s++) csl[s] = 0.f;
        #pragma unroll
        for (int nt = 0; nt < 4; nt++) {
            #pragma unroll
            for (int mt = 0; mt < 4; mt++) {
                // q pairs (0,1) and (2,3) share the es slot; split across csl
                uint32_t p01 = ex2_h2(pack_h2(acc[mt][nt][0], acc[mt][nt][1]));
                uint32_t p23 = ex2_h2(pack_h2(acc[mt][nt][2], acc[mt][nt][3]));
                float2 e01 = __half22float2(*reinterpret_cast<__half2*>(&p01));
                float2 e23 = __half22float2(*reinterpret_cast<__half2*>(&p23));
                float ev[4] = {e01.x, e01.y, e23.x, e23.y};
                if (isdiag) {
                    #pragma unroll
                    for (int q = 0; q < 4; q++) {
                        int jl = warp_n * 32 + nt * 8 + (lane & 3) * 2 + (q & 1);
                        int il = warp_m * 64 + mt * 16 + (lane >> 2) + ((q < 2) ? 0 : 8);
                        if (jl == il) ev[q] = 0.f;
                    }
                }
                es[mt * 2 + 0] += ev[0] + ev[1];
                es[mt * 2 + 1] += ev[2] + ev[3];
                csl[nt * 2 + 0] += ev[0] + ev[2];
                csl[nt * 2 + 1] += ev[1] + ev[3];
            }
        }
        if (!isdiag) {
            int colBase = tc * TM;
            #pragma unroll
            for (int s = 0; s < 8; s++) {
                float v = csl[s];
                v += __shfl_xor_sync(0xffffffffu, v, 4);
                v += __shfl_xor_sync(0xffffffffu, v, 8);
                v += __shfl_xor_sync(0xffffffffu, v, 16);
                if (lane < 4)
                    atomicAdd(&g_S[colBase + warp_n * 32 + (s >> 1) * 8 + lane * 2 + (s & 1)], v);
            }
        }

        if (havenext && nr != tr) {
            int rowBase = accr * TM;
            #pragma unroll
            for (int s = 0; s < 8; s++) {
                float e = es[s];
                e += __shfl_xor_sync(0xffffffffu, e, 1);
                e += __shfl_xor_sync(0xffffffffu, e, 2);
                if ((lane & 3) == 0)
                    atomicAdd(&g_S[rowBase + warp_m * 64 + (s >> 1) * 16 +
                                   (lane >> 2) + (s & 1) * 8], e);
                es[s] = 0.f;
            }
            accr = nr;
            __syncthreads();
            load_tile(smb + A_OFF, g_phA, nr * TM, tid);
            CP_COMMIT();
        }
        r = nr; c = nc; parity ^= 1;
    }

    {
        int rowBase = accr * TM;
        #pragma unroll
        for (int s = 0; s < 8; s++) {
            float e = es[s];
            e += __shfl_xor_sync(0xffffffffu, e, 1);
            e += __shfl_xor_sync(0xffffffffu, e, 2);
            if ((lane & 3) == 0)
                atomicAdd(&g_S[rowBase + warp_m * 64 + (s >> 1) * 16 +
                               (lane >> 2) + (s & 1) * 8], e);
        }
    }
#undef AADDR
#undef BADDR
}

// ---------------------------------------------------------------------------
// Kernel 3: finalize. GFIN x 256, 256 rows per block (one per thread for logs).
// Class sums from f16 table (32 rows per warp, MLP-unrolled). Ticketed
// class-norm term; last block resets g_cls/g_cnt/g_ticket.
// ---------------------------------------------------------------------------
__global__ __launch_bounds__(256)
void finalize_kernel(const int* __restrict__ y, int B, float* __restrict__ out) {
    __shared__ float ws[8];
    __shared__ float cls_b[2][D];
    __shared__ int   cnt_b;
    __shared__ bool  is_last;
    int t = threadIdx.x, lane = t & 31, warp = t >> 5;
    if (t < 2 * D) ((float*)cls_b)[t] = 0.f;
    if (t == 0) cnt_b = 0;

    // (a) log part — one row per thread
    float local = __logf(g_S[blockIdx.x * 256 + t]);
    #pragma unroll
    for (int o = 16; o > 0; o >>= 1) local += __shfl_xor_sync(0xffffffffu, local, o);
    if (lane == 0) ws[warp] = local;
    __syncthreads();
    if (t < 8) {
        float v = ws[t];
        #pragma unroll
        for (int o = 4; o > 0; o >>= 1) v += __shfl_xor_sync(0x000000ffu, v, o);
        if (t == 0) atomicAdd(out, v);
    }

    // (b) class sums from f16 table: warp handles 32 rows, lane = 4 dims
    float a0[4] = {0.f, 0.f, 0.f, 0.f}, a1[4] = {0.f, 0.f, 0.f, 0.f};
    int   c1 = 0;
    int rb = blockIdx.x * 256 + warp * 32;
    #pragma unroll 8
    for (int i = 0; i < 32; i++) {
        int row = rb + i;
        int lbl = (row < B) ? y[row] : y[row - B];
        uint2 u = ((const uint2*)(g_ph + (size_t)row * D))[lane];
        __half2 h0 = *reinterpret_cast<__half2*>(&u.x);
        __half2 h1 = *reinterpret_cast<__half2*>(&u.y);
        float2 f0 = __half22float2(h0), f1 = __half22float2(h1);
        if (lbl) {
            a1[0] += f0.x; a1[1] += f0.y; a1[2] += f1.x; a1[3] += f1.y; c1++;
        } else {
            a0[0] += f0.x; a0[1] += f0.y; a0[2] += f1.x; a0[3] += f1.y;
        }
    }
    #pragma unroll
    for (int k = 0; k < 4; k++) {
        atomicAdd(&cls_b[0][lane * 4 + k], a0[k]);
        atomicAdd(&cls_b[1][lane * 4 + k], a1[k]);
    }
    if (lane == 0) atomicAdd(&cnt_b, c1);
    __syncthreads();
    if (t < 2 * D) atomicAdd(&((float*)g_cls)[t], ((float*)cls_b)[t]);
    if (t == 0) atomicAdd(&g_cnt[1], cnt_b);

    // (c) last block: class-norm term + reset
    __threadfence();
    __syncthreads();
    if (t == 0) is_last = (atomicAdd(&g_ticket, 1u) == (unsigned)(GFIN - 1));
    __syncthreads();
    if (!is_last) return;
    __threadfence();

    if (warp < 2) {
        float4 cv = ((const float4*)(g_cls[warp]))[lane];
        float nsq = cv.x * cv.x + cv.y * cv.y + cv.z * cv.z + cv.w * cv.w;
        #pragma unroll
        for (int o = 16; o > 0; o >>= 1) nsq += __shfl_xor_sync(0xffffffffu, nsq, o);
        if (lane == 0) {
            float cnt = (warp == 1) ? (float)g_cnt[1] : (float)(NMAX - g_cnt[1]);
            atomicAdd(out, -TAU_INV * (nsq - cnt) / (cnt - 1.f));
        }
    }
    __syncthreads();
    if (t < 2 * D) ((float*)g_cls)[t] = 0.f;
    if (t < 2) g_cnt[t] = 0;
    if (t == 0) g_ticket = 0u;
}

// ---------------------------------------------------------------------------
extern "C" void kernel_launch(void* const* d_in, const int* in_sizes, int n_in,
                              void* d_out, int out_size) {
    const float* zi = (const float*)d_in[0];
    const float* zj = (const float*)d_in[1];
    const int*   y  = (const int*)d_in[2];
    int B = in_sizes[2];
    int N = 2 * B;

    prep_kernel<<<N / 8, 256>>>(zi, zj, B, (float*)d_out);

    cudaFuncSetAttribute(main_kernel, cudaFuncAttributeMaxDynamicSharedMemorySize,
                         SMEM_TOTAL);
    main_kernel<<<GMAIN, 256, SMEM_TOTAL>>>();

    finalize_kernel<<<GFIN, 256>>>(y, B, (float*)d_out);
}

// round 15
// speedup vs baseline: 1.0397x; 1.0375x over previous
#include <cuda_runtime.h>
#include <cuda_fp16.h>
#include <cstdint>
#include <math.h>

#define D       128
#define NMAX    8192
#define TAU_INV 10.0f
#define EX2K    14.4269504088896f   // TAU_INV * log2(e)
#define TM      128
#define NTT     64                  // tiles per dimension
#define NTILES_TRI (NTT * (NTT + 1) / 2)   // 2080
#define GMAIN   296                 // 2 CTAs per SM, persistent
#define GFIN    32                  // finalize blocks (256 rows each)

// scratch (device globals; no allocation allowed). g_cls/g_cnt/g_ticket are
// restored to zero by finalize's last block each run.
__device__ __half g_ph[NMAX * D];      // normalized rows, f16 (B operand)
__device__ __half g_phA[NMAX * D];     // normalized rows * EX2K, f16 (A operand)
__device__ float  g_S[NMAX];           // exp-sum accumulators (zeroed by prep)
__device__ float  g_cls[2][D];         // per-class vector sums (from f16 table)
__device__ int    g_cnt[2];
__device__ unsigned int g_ticket;

// ---------------------------------------------------------------------------
__device__ __forceinline__ uint32_t smem_u32(const void* p) {
    uint32_t a;
    asm("{ .reg .u64 t; cvta.to.shared.u64 t, %1; cvt.u32.u64 %0, t; }"
        : "=r"(a) : "l"(p));
    return a;
}
__device__ __forceinline__ void ldsm4(uint32_t r[4], uint32_t addr) {
    asm volatile("ldmatrix.sync.aligned.m8n8.x4.shared.b16 {%0,%1,%2,%3}, [%4];"
                 : "=r"(r[0]), "=r"(r[1]), "=r"(r[2]), "=r"(r[3]) : "r"(addr));
}
// non-volatile — lets ptxas schedule MMAs between/around the LDSMs.
__device__ __forceinline__ void mma16816(float c[4], const uint32_t a[4],
                                         const uint32_t b[2]) {
    asm("mma.sync.aligned.m16n8k16.row.col.f32.f16.f16.f32 "
        "{%0,%1,%2,%3}, {%4,%5,%6,%7}, {%8,%9}, {%0,%1,%2,%3};"
        : "+f"(c[0]), "+f"(c[1]), "+f"(c[2]), "+f"(c[3])
        : "r"(a[0]), "r"(a[1]), "r"(a[2]), "r"(a[3]), "r"(b[0]), "r"(b[1]));
}
__device__ __forceinline__ void cp16(uint32_t saddr, const void* g) {
    asm volatile("cp.async.cg.shared.global [%0], [%1], 16;"
                 :: "r"(saddr), "l"(g) : "memory");
}
__device__ __forceinline__ float ex2(float x) {
    float r;
    asm("ex2.approx.f32 %0, %1;" : "=f"(r) : "f"(x));
    return r;
}
// packed fp32 accumulate: acc += v  (FADD2; PTX f32x2 requires sm_100+ family)
__device__ __forceinline__ void addx2(float2& acc, float vx, float vy) {
    unsigned long long a, b;
    asm("mov.b64 %0, {%1, %2};" : "=l"(a) : "f"(acc.x), "f"(acc.y));
    asm("mov.b64 %0, {%1, %2};" : "=l"(b) : "f"(vx), "f"(vy));
    asm("add.rn.f32x2 %0, %0, %1;" : "+l"(a) : "l"(b));
    asm("mov.b64 {%0, %1}, %2;" : "=f"(acc.x), "=f"(acc.y) : "l"(a));
}
#define CP_COMMIT() asm volatile("cp.async.commit_group;" ::: "memory")
#define CP_WAIT(n)  asm volatile("cp.async.wait_group %0;" :: "n"(n) : "memory")

#define A_OFF  0u
#define B0_OFF 32768u
#define B1_OFF 65536u
#define SMEM_TOTAL 98304

// ---------------------------------------------------------------------------
// Kernel 1: pure streaming prep (R12, unchanged).
// ---------------------------------------------------------------------------
__global__ __launch_bounds__(256)
void prep_kernel(const float* __restrict__ zi,
                 const float* __restrict__ zj,
                 int B, float* __restrict__ out) {
    int warp = threadIdx.x >> 5, lane = threadIdx.x & 31;
    int row  = blockIdx.x * 8 + warp;
    if (blockIdx.x == 0 && threadIdx.x == 0) out[0] = 0.f;

    const float* src = (row < B) ? (zi + (size_t)row * D)
                                 : (zj + (size_t)(row - B) * D);
    float4 v = ((const float4*)src)[lane];
    float ss = v.x * v.x + v.y * v.y + v.z * v.z + v.w * v.w;
    #pragma unroll
    for (int o = 16; o > 0; o >>= 1) ss += __shfl_xor_sync(0xffffffffu, ss, o);
    float s = 1.f / fmaxf(sqrtf(ss), 1e-8f);
    float4 pn = make_float4(v.x * s, v.y * s, v.z * s, v.w * s);

    __half2 h0 = __floats2half2_rn(pn.x, pn.y);
    __half2 h1 = __floats2half2_rn(pn.z, pn.w);
    uint2 u;
    u.x = *reinterpret_cast<unsigned int*>(&h0);
    u.y = *reinterpret_cast<unsigned int*>(&h1);
    ((uint2*)(g_ph + (size_t)row * D))[lane] = u;

    __half2 a0 = __floats2half2_rn(pn.x * EX2K, pn.y * EX2K);
    __half2 a1 = __floats2half2_rn(pn.z * EX2K, pn.w * EX2K);
    uint2 ua;
    ua.x = *reinterpret_cast<unsigned int*>(&a0);
    ua.y = *reinterpret_cast<unsigned int*>(&a1);
    ((uint2*)(g_phA + (size_t)row * D))[lane] = ua;

    if (lane == 0) g_S[row] = 0.f;
}

// ---------------------------------------------------------------------------
__device__ __forceinline__ void load_tile(uint32_t dst, const __half* table,
                                          int base, int tid) {
    for (int u = tid; u < TM * 16; u += 256) {
        int rr = u >> 4, cc = u & 15;
        cp16(dst + (uint32_t)rr * 256u + (uint32_t)((cc ^ (rr & 7)) << 4),
             table + (size_t)(base + rr) * D + cc * 8);
    }
}

// ---------------------------------------------------------------------------
// Kernel 2: persistent symmetric HMMA (R12 structure), fp32 ex2 epilogue with
// packed-f32x2 accumulators (es/csl as float2, FADD2).
// ---------------------------------------------------------------------------
__global__ __launch_bounds__(256, 2)
void main_kernel() {
    extern __shared__ char sm[];
    const uint32_t smb = smem_u32(sm);

    const int tid = threadIdx.x, lane = tid & 31, wid = tid >> 5;
    const int warp_m = wid >> 2, warp_n = wid & 3;

    const int lo = (int)(((long long)blockIdx.x * NTILES_TRI) / GMAIN);
    const int hi = (int)(((long long)(blockIdx.x + 1) * NTILES_TRI) / GMAIN);

    int r = 0;
    while ((r + 1) * (2 * NTT - r) / 2 <= lo) r++;
    int c = r + (lo - r * (2 * NTT - r + 1) / 2);

    load_tile(smb + A_OFF, g_phA, r * TM, tid);
    load_tile(smb + B0_OFF, g_ph, c * TM, tid);
    CP_COMMIT();

    const int g = lane >> 3;
    uint32_t a_off[4], a_msk[4];
    #pragma unroll
    for (int mt = 0; mt < 4; mt++) {
        int row = warp_m * 64 + mt * 16 + (g & 1) * 8 + (lane & 7);
        a_off[mt] = smb + A_OFF + (uint32_t)row * 256u;
        a_msk[mt] = (uint32_t)(row & 7);
    }
    const int a_cadd = g >> 1;
    uint32_t b_row[2], b_msk[2];
    #pragma unroll
    for (int nt2 = 0; nt2 < 2; nt2++) {
        int row = warp_n * 32 + nt2 * 16 + (g >> 1) * 8 + (lane & 7);
        b_row[nt2] = (uint32_t)row * 256u;
        b_msk[nt2] = (uint32_t)(row & 7);
    }
    const int b_cadd = g & 1;

#define AADDR(mt, ks) (a_off[mt] + (uint32_t)(((2 * (ks) + a_cadd) ^ a_msk[mt]) << 4))
#define BADDR(n2, ks) (bbase + b_row[n2] + (uint32_t)(((2 * (ks) + b_cadd) ^ b_msk[n2]) << 4))

    // esp[mt].x = row slot (mt,0) [q0,q1 rows], .y = row slot (mt,1) [q2,q3]
    float2 esp[4];
    #pragma unroll
    for (int s = 0; s < 4; s++) esp[s] = make_float2(0.f, 0.f);
    int parity = 0;
    int accr = r;

    for (int t = lo; t < hi; t++) {
        const int tr = r, tc = c;
        const bool isdiag = (tr == tc);
        int nr = r, nc = c + 1;
        if (nc == NTT) { nr = r + 1; nc = nr; }
        const bool havenext = (t + 1 < hi);

        __syncthreads();
        if (havenext) {
            load_tile(smb + (parity ? B0_OFF : B1_OFF), g_ph, nc * TM, tid);
            CP_COMMIT();
            CP_WAIT(1);
        } else {
            CP_WAIT(0);
        }
        __syncthreads();

        const uint32_t bbase = smb + (parity ? B1_OFF : B0_OFF);
        float acc[4][4][4];
        #pragma unroll
        for (int mt = 0; mt < 4; mt++)
            #pragma unroll
            for (int nt = 0; nt < 4; nt++)
                #pragma unroll
                for (int k = 0; k < 4; k++) acc[mt][nt][k] = 0.f;

        uint32_t afb[2][4], bfb[2][2][4];
        ldsm4(bfb[0][0], BADDR(0, 0));
        ldsm4(bfb[0][1], BADDR(1, 0));
        ldsm4(afb[0], AADDR(0, 0));
        #pragma unroll
        for (int ks = 0; ks < 8; ks++) {
            const int kb = ks & 1;
            if (ks < 7) {
                ldsm4(bfb[kb ^ 1][0], BADDR(0, ks + 1));
                ldsm4(bfb[kb ^ 1][1], BADDR(1, ks + 1));
            }
            #pragma unroll
            for (int mt = 0; mt < 4; mt++) {
                const int ab = mt & 1;
                if (mt < 3)      ldsm4(afb[ab ^ 1], AADDR(mt + 1, ks));
                else if (ks < 7) ldsm4(afb[ab ^ 1], AADDR(0, ks + 1));
                #pragma unroll
                for (int nt = 0; nt < 4; nt++)
                    mma16816(acc[mt][nt], afb[ab], &bfb[kb][nt >> 1][(nt & 1) * 2]);
            }
        }

        // ---- epilogue: fp32 ex2, packed-f32x2 row + column accumulation -------
        float2 cslp[4];   // cslp[nt].x = col j0, .y = col j0+1
        #pragma unroll
        for (int s = 0; s < 4; s++) cslp[s] = make_float2(0.f, 0.f);
        #pragma unroll
        for (int nt = 0; nt < 4; nt++) {
            #pragma unroll
            for (int mt = 0; mt < 4; mt++) {
                float e0 = ex2(acc[mt][nt][0]);
                float e1 = ex2(acc[mt][nt][1]);
                float e2 = ex2(acc[mt][nt][2]);
                float e3 = ex2(acc[mt][nt][3]);
                if (isdiag) {
                    int j0 = warp_n * 32 + nt * 8 + (lane & 3) * 2;
                    int i0 = warp_m * 64 + mt * 16 + (lane >> 2);
                    if (j0     == i0)     e0 = 0.f;
                    if (j0 + 1 == i0)     e1 = 0.f;
                    if (j0     == i0 + 8) e2 = 0.f;
                    if (j0 + 1 == i0 + 8) e3 = 0.f;
                }
                addx2(esp[mt], e0 + e1, e2 + e3);
                addx2(cslp[nt], e0, e1);
                addx2(cslp[nt], e2, e3);
            }
        }
        if (!isdiag) {
            int colBase = tc * TM;
            #pragma unroll
            for (int s = 0; s < 8; s++) {
                float v = (s & 1) ? cslp[s >> 1].y : cslp[s >> 1].x;
                v += __shfl_xor_sync(0xffffffffu, v, 4);
                v += __shfl_xor_sync(0xffffffffu, v, 8);
                v += __shfl_xor_sync(0xffffffffu, v, 16);
                if (lane < 4)
                    atomicAdd(&g_S[colBase + warp_n * 32 + (s >> 1) * 8 + lane * 2 + (s & 1)], v);
            }
        }

        if (havenext && nr != tr) {
            int rowBase = accr * TM;
            #pragma unroll
            for (int s = 0; s < 8; s++) {
                float e = (s & 1) ? esp[s >> 1].y : esp[s >> 1].x;
                e += __shfl_xor_sync(0xffffffffu, e, 1);
                e += __shfl_xor_sync(0xffffffffu, e, 2);
                if ((lane & 3) == 0)
                    atomicAdd(&g_S[rowBase + warp_m * 64 + (s >> 1) * 16 +
                                   (lane >> 2) + (s & 1) * 8], e);
            }
            #pragma unroll
            for (int s = 0; s < 4; s++) esp[s] = make_float2(0.f, 0.f);
            accr = nr;
            __syncthreads();
            load_tile(smb + A_OFF, g_phA, nr * TM, tid);
            CP_COMMIT();
        }
        r = nr; c = nc; parity ^= 1;
    }

    // final row flush — accr owns the esp[] accumulations
    {
        int rowBase = accr * TM;
        #pragma unroll
        for (int s = 0; s < 8; s++) {
            float e = (s & 1) ? esp[s >> 1].y : esp[s >> 1].x;
            e += __shfl_xor_sync(0xffffffffu, e, 1);
            e += __shfl_xor_sync(0xffffffffu, e, 2);
            if ((lane & 3) == 0)
                atomicAdd(&g_S[rowBase + warp_m * 64 + (s >> 1) * 16 +
                               (lane >> 2) + (s & 1) * 8], e);
        }
    }
#undef AADDR
#undef BADDR
}

// ---------------------------------------------------------------------------
// Kernel 3: finalize (R14 lean version, proven). GFIN x 256, 256 rows/block.
// ---------------------------------------------------------------------------
__global__ __launch_bounds__(256)
void finalize_kernel(const int* __restrict__ y, int B, float* __restrict__ out) {
    __shared__ float ws[8];
    __shared__ float cls_b[2][D];
    __shared__ int   cnt_b;
    __shared__ bool  is_last;
    int t = threadIdx.x, lane = t & 31, warp = t >> 5;
    if (t < 2 * D) ((float*)cls_b)[t] = 0.f;
    if (t == 0) cnt_b = 0;

    float local = __logf(g_S[blockIdx.x * 256 + t]);
    #pragma unroll
    for (int o = 16; o > 0; o >>= 1) local += __shfl_xor_sync(0xffffffffu, local, o);
    if (lane == 0) ws[warp] = local;
    __syncthreads();
    if (t < 8) {
        float v = ws[t];
        #pragma unroll
        for (int o = 4; o > 0; o >>= 1) v += __shfl_xor_sync(0x000000ffu, v, o);
        if (t == 0) atomicAdd(out, v);
    }

    float a0[4] = {0.f, 0.f, 0.f, 0.f}, a1[4] = {0.f, 0.f, 0.f, 0.f};
    int   c1 = 0;
    int rb = blockIdx.x * 256 + warp * 32;
    #pragma unroll 8
    for (int i = 0; i < 32; i++) {
        int row = rb + i;
        int lbl = (row < B) ? y[row] : y[row - B];
        uint2 u = ((const uint2*)(g_ph + (size_t)row * D))[lane];
        __half2 h0 = *reinterpret_cast<__half2*>(&u.x);
        __half2 h1 = *reinterpret_cast<__half2*>(&u.y);
        float2 f0 = __half22float2(h0), f1 = __half22float2(h1);
        if (lbl) {
            a1[0] += f0.x; a1[1] += f0.y; a1[2] += f1.x; a1[3] += f1.y; c1++;
        } else {
            a0[0] += f0.x; a0[1] += f0.y; a0[2] += f1.x; a0[3] += f1.y;
        }
    }
    #pragma unroll
    for (int k = 0; k < 4; k++) {
        atomicAdd(&cls_b[0][lane * 4 + k], a0[k]);
        atomicAdd(&cls_b[1][lane * 4 + k], a1[k]);
    }
    if (lane == 0) atomicAdd(&cnt_b, c1);
    __syncthreads();
    if (t < 2 * D) atomicAdd(&((float*)g_cls)[t], ((float*)cls_b)[t]);
    if (t == 0) atomicAdd(&g_cnt[1], cnt_b);

    __threadfence();
    __syncthreads();
    if (t == 0) is_last = (atomicAdd(&g_ticket, 1u) == (unsigned)(GFIN - 1));
    __syncthreads();
    if (!is_last) return;
    __threadfence();

    if (warp < 2) {
        float4 cv = ((const float4*)(g_cls[warp]))[lane];
        float nsq = cv.x * cv.x + cv.y * cv.y + cv.z * cv.z + cv.w * cv.w;
        #pragma unroll
        for (int o = 16; o > 0; o >>= 1) nsq += __shfl_xor_sync(0xffffffffu, nsq, o);
        if (lane == 0) {
            float cnt = (warp == 1) ? (float)g_cnt[1] : (float)(NMAX - g_cnt[1]);
            atomicAdd(out, -TAU_INV * (nsq - cnt) / (cnt - 1.f));
        }
    }
    __syncthreads();
    if (t < 2 * D) ((float*)g_cls)[t] = 0.f;
    if (t < 2) g_cnt[t] = 0;
    if (t == 0) g_ticket = 0u;
}

// ---------------------------------------------------------------------------
extern "C" void kernel_launch(void* const* d_in, const int* in_sizes, int n_in,
                              void* d_out, int out_size) {
    const float* zi = (const float*)d_in[0];
    const float* zj = (const float*)d_in[1];
    const int*   y  = (const int*)d_in[2];
    int B = in_sizes[2];
    int N = 2 * B;

    prep_kernel<<<N / 8, 256>>>(zi, zj, B, (float*)d_out);

    cudaFuncSetAttribute(main_kernel, cudaFuncAttributeMaxDynamicSharedMemorySize,
                         SMEM_TOTAL);
    main_kernel<<<GMAIN, 256, SMEM_TOTAL>>>();

    finalize_kernel<<<GFIN, 256>>>(y, B, (float*)d_out);
}